// round 2
// baseline (speedup 1.0000x reference)
#include <cuda_runtime.h>
#include <math.h>

#define IN_DIM   784
#define HIDDEN   512
#define STYLE    128
#define BATCH    2048
#define NUM_LABELS 10

#define BM 64
#define BK 16
#define MAX_TILES (BATCH / BM + NUM_LABELS)   // 42

// Scratch (no allocations allowed -> __device__ globals)
__device__ int   g_perm[BATCH];
__device__ int   g_tileGroup[MAX_TILES];
__device__ int   g_tileStart[MAX_TILES];
__device__ int   g_tileRows[MAX_TILES];
__device__ float g_h1[(BATCH + BM) * HIDDEN];   // padded one tile for safe over-read

// ---------------------------------------------------------------------------
// Kernel 1: group samples by label (counting sort) + build padded tile table.
// One block. Order within a group is atomic-nondeterministic but output values
// are order-invariant, so the final d_out is deterministic.
// ---------------------------------------------------------------------------
__global__ void group_kernel(const int* __restrict__ m) {
    __shared__ int cnt[NUM_LABELS];
    __shared__ int off[NUM_LABELS];
    int t = threadIdx.x;
    if (t < NUM_LABELS) cnt[t] = 0;
    __syncthreads();
    for (int i = t; i < BATCH; i += blockDim.x) atomicAdd(&cnt[m[i]], 1);
    __syncthreads();
    if (t == 0) {
        int o = 0, tile = 0;
        for (int g = 0; g < NUM_LABELS; g++) {
            off[g] = o;
            int c = cnt[g];
            int nt = (c + BM - 1) / BM;
            for (int j = 0; j < nt; j++) {
                g_tileGroup[tile] = g;
                g_tileStart[tile] = o + j * BM;
                g_tileRows[tile]  = min(BM, c - j * BM);
                tile++;
            }
            o += c;
        }
        for (; tile < MAX_TILES; tile++) g_tileRows[tile] = 0;
    }
    __syncthreads();
    for (int i = t; i < BATCH; i += blockDim.x) {
        int g = m[i];
        int p = atomicAdd(&off[g], 1);
        g_perm[p] = i;
    }
}

// ---------------------------------------------------------------------------
// Kernel 2: FC1 GEMM.  Per (row-tile, col-tile): 64x128 output tile, K=784.
// A rows gathered through g_perm; W shared by all rows in the tile (one label).
// Epilogue: +bias, ReLU, store to g_h1 in PERMUTED row order (dense).
// ---------------------------------------------------------------------------
__global__ __launch_bounds__(256) void fc1_kernel(const float* __restrict__ x,
                                                  const float* __restrict__ fc1_table) {
    int tile = blockIdx.y;
    int rows = g_tileRows[tile];
    if (rows == 0) return;
    int g     = g_tileGroup[tile];
    int start = g_tileStart[tile];
    int n0    = blockIdx.x * 128;
    const float* W = fc1_table + (size_t)g * ((IN_DIM + 1) * HIDDEN);

    __shared__ float Xs[BM][BK];
    __shared__ float Ws[BK][128];
    __shared__ int   rowIdx[BM];

    int t = threadIdx.x;
    if (t < BM) rowIdx[t] = (t < rows) ? g_perm[start + t] : -1;
    __syncthreads();

    float acc[8][4];
#pragma unroll
    for (int i = 0; i < 8; i++)
#pragma unroll
        for (int j = 0; j < 4; j++) acc[i][j] = 0.f;

    int row_t = t >> 5;   // 0..7  (same within a warp -> Xs reads broadcast)
    int col_t = t & 31;   // 0..31 (float4 column -> conflict-free LDS.128)

    for (int k0 = 0; k0 < IN_DIM; k0 += BK) {
        // Load Xs: 64x16 = 1024 floats, 4 per thread (gathered rows)
#pragma unroll
        for (int l = 0; l < 4; l++) {
            int idx = t + l * 256;
            int r   = idx >> 4;
            int kk  = idx & 15;
            int gr  = rowIdx[r];
            Xs[r][kk] = (gr >= 0) ? x[(size_t)gr * IN_DIM + k0 + kk] : 0.f;
        }
        // Load Ws: 16x128 floats = 512 float4, 2 per thread, fully coalesced
#pragma unroll
        for (int l = 0; l < 2; l++) {
            int idx = t + l * 256;
            int kk  = idx >> 5;
            int c4  = idx & 31;
            *(float4*)&Ws[kk][c4 * 4] =
                *(const float4*)&W[(size_t)(k0 + kk) * HIDDEN + n0 + c4 * 4];
        }
        __syncthreads();
#pragma unroll
        for (int kk = 0; kk < BK; kk++) {
            float4 b = *(float4*)&Ws[kk][col_t * 4];
#pragma unroll
            for (int i = 0; i < 8; i++) {
                float a = Xs[row_t * 8 + i][kk];
                acc[i][0] += a * b.x;
                acc[i][1] += a * b.y;
                acc[i][2] += a * b.z;
                acc[i][3] += a * b.w;
            }
        }
        __syncthreads();
    }

    const float* bias = W + (size_t)IN_DIM * HIDDEN;
    float4 bb = *(const float4*)&bias[n0 + col_t * 4];
#pragma unroll
    for (int i = 0; i < 8; i++) {
        int r = row_t * 8 + i;
        if (r < rows) {
            float4 v;
            v.x = fmaxf(acc[i][0] + bb.x, 0.f);
            v.y = fmaxf(acc[i][1] + bb.y, 0.f);
            v.z = fmaxf(acc[i][2] + bb.z, 0.f);
            v.w = fmaxf(acc[i][3] + bb.w, 0.f);
            *(float4*)&g_h1[(size_t)(start + r) * HIDDEN + n0 + col_t * 4] = v;
        }
    }
}

// ---------------------------------------------------------------------------
// Kernel 3: FC2 GEMM.  64x128 tile, K=512.  A = g_h1 (already permuted, dense).
// Epilogue: +bias, sigmoid, scatter to d_out via g_perm.
// ---------------------------------------------------------------------------
__global__ __launch_bounds__(256) void fc2_kernel(const float* __restrict__ fc2_table,
                                                  float* __restrict__ out) {
    int tile = blockIdx.x;
    int rows = g_tileRows[tile];
    if (rows == 0) return;
    int g     = g_tileGroup[tile];
    int start = g_tileStart[tile];
    const float* W = fc2_table + (size_t)g * ((HIDDEN + 1) * STYLE);

    __shared__ float Xs[BM][BK];
    __shared__ float Ws[BK][STYLE];
    __shared__ int   rowIdx[BM];

    int t = threadIdx.x;
    if (t < BM) rowIdx[t] = (t < rows) ? g_perm[start + t] : -1;
    __syncthreads();

    float acc[8][4];
#pragma unroll
    for (int i = 0; i < 8; i++)
#pragma unroll
        for (int j = 0; j < 4; j++) acc[i][j] = 0.f;

    int row_t = t >> 5;
    int col_t = t & 31;

    for (int k0 = 0; k0 < HIDDEN; k0 += BK) {
        // A from permuted h1 (padded rows read harmless in-bounds garbage;
        // their outputs are discarded by the r<rows store guard)
#pragma unroll
        for (int l = 0; l < 4; l++) {
            int idx = t + l * 256;
            int r   = idx >> 4;
            int kk  = idx & 15;
            Xs[r][kk] = g_h1[(size_t)(start + r) * HIDDEN + k0 + kk];
        }
#pragma unroll
        for (int l = 0; l < 2; l++) {
            int idx = t + l * 256;
            int kk  = idx >> 5;
            int c4  = idx & 31;
            *(float4*)&Ws[kk][c4 * 4] =
                *(const float4*)&W[(size_t)(k0 + kk) * STYLE + c4 * 4];
        }
        __syncthreads();
#pragma unroll
        for (int kk = 0; kk < BK; kk++) {
            float4 b = *(float4*)&Ws[kk][col_t * 4];
#pragma unroll
            for (int i = 0; i < 8; i++) {
                float a = Xs[row_t * 8 + i][kk];
                acc[i][0] += a * b.x;
                acc[i][1] += a * b.y;
                acc[i][2] += a * b.z;
                acc[i][3] += a * b.w;
            }
        }
        __syncthreads();
    }

    const float* bias = W + (size_t)HIDDEN * STYLE;
    float4 bb = *(const float4*)&bias[col_t * 4];
#pragma unroll
    for (int i = 0; i < 8; i++) {
        int r = row_t * 8 + i;
        if (r < rows) {
            int orow = rowIdx[r];
            float4 v;
            v.x = 1.f / (1.f + __expf(-(acc[i][0] + bb.x)));
            v.y = 1.f / (1.f + __expf(-(acc[i][1] + bb.y)));
            v.z = 1.f / (1.f + __expf(-(acc[i][2] + bb.z)));
            v.w = 1.f / (1.f + __expf(-(acc[i][3] + bb.w)));
            *(float4*)&out[(size_t)orow * STYLE + col_t * 4] = v;
        }
    }
}

extern "C" void kernel_launch(void* const* d_in, const int* in_sizes, int n_in,
                              void* d_out, int out_size) {
    const float* x         = (const float*)d_in[0];
    const int*   m         = (const int*)d_in[1];
    const float* fc1_table = (const float*)d_in[2];
    const float* fc2_table = (const float*)d_in[3];
    float*       out       = (float*)d_out;

    group_kernel<<<1, 1024>>>(m);
    fc1_kernel<<<dim3(HIDDEN / 128, MAX_TILES), 256>>>(x, fc1_table);
    fc2_kernel<<<MAX_TILES, 256>>>(fc2_table, out);
}

// round 4
// speedup vs baseline: 4.7616x; 4.7616x over previous
#include <cuda_runtime.h>
#include <cuda_bf16.h>
#include <math.h>
#include <stdint.h>

#define IN_DIM   784
#define HIDDEN   512
#define STYLE    128
#define BATCH    2048
#define NUM_LABELS 10

#define BM 64
#define MAX_TILES (BATCH / BM + NUM_LABELS)   // 42

// Scratch (no allocations allowed -> __device__ globals)
__device__ int   g_perm[BATCH];
__device__ int   g_tileGroup[MAX_TILES];
__device__ int   g_tileStart[MAX_TILES];
__device__ int   g_tileRows[MAX_TILES];
__device__ __nv_bfloat16 g_h1[(BATCH + BM) * HIDDEN];  // bf16, padded one tile

// ---------------------------------------------------------------------------
// Helpers
// ---------------------------------------------------------------------------
__device__ __forceinline__ uint32_t f2bf2(float lo, float hi) {
    __nv_bfloat162 h = __floats2bfloat162_rn(lo, hi);   // .x = lo (low half)
    return *reinterpret_cast<uint32_t*>(&h);
}

__device__ __forceinline__ void ldsm_x4(uint32_t& r0, uint32_t& r1, uint32_t& r2, uint32_t& r3,
                                        uint32_t saddr) {
    asm volatile("ldmatrix.sync.aligned.m8n8.x4.shared.b16 {%0,%1,%2,%3}, [%4];"
                 : "=r"(r0), "=r"(r1), "=r"(r2), "=r"(r3) : "r"(saddr));
}

__device__ __forceinline__ void ldsm_x4_t(uint32_t& r0, uint32_t& r1, uint32_t& r2, uint32_t& r3,
                                          uint32_t saddr) {
    asm volatile("ldmatrix.sync.aligned.m8n8.x4.trans.shared.b16 {%0,%1,%2,%3}, [%4];"
                 : "=r"(r0), "=r"(r1), "=r"(r2), "=r"(r3) : "r"(saddr));
}

__device__ __forceinline__ void mma16816(float* c, const uint32_t* a, const uint32_t* b) {
    asm volatile("mma.sync.aligned.m16n8k16.row.col.f32.bf16.bf16.f32 "
                 "{%0,%1,%2,%3}, {%4,%5,%6,%7}, {%8,%9}, {%0,%1,%2,%3};"
                 : "+f"(c[0]), "+f"(c[1]), "+f"(c[2]), "+f"(c[3])
                 : "r"(a[0]), "r"(a[1]), "r"(a[2]), "r"(a[3]), "r"(b[0]), "r"(b[1]));
}

// ---------------------------------------------------------------------------
// Kernel 1: group samples by label (counting sort) + padded tile table.
// Per-sample outputs are order-invariant, so atomic nondeterminism in the
// permutation does not change d_out values.
// ---------------------------------------------------------------------------
__global__ void group_kernel(const int* __restrict__ m) {
    __shared__ int cnt[NUM_LABELS];
    __shared__ int off[NUM_LABELS];
    int t = threadIdx.x;
    if (t < NUM_LABELS) cnt[t] = 0;
    __syncthreads();
    for (int i = t; i < BATCH; i += blockDim.x) atomicAdd(&cnt[m[i]], 1);
    __syncthreads();
    if (t == 0) {
        int o = 0, tile = 0;
        for (int g = 0; g < NUM_LABELS; g++) {
            off[g] = o;
            int c = cnt[g];
            int nt = (c + BM - 1) / BM;
            for (int j = 0; j < nt; j++) {
                g_tileGroup[tile] = g;
                g_tileStart[tile] = o + j * BM;
                g_tileRows[tile]  = min(BM, c - j * BM);
                tile++;
            }
            o += c;
        }
        for (; tile < MAX_TILES; tile++) g_tileRows[tile] = 0;
    }
    __syncthreads();
    for (int i = t; i < BATCH; i += blockDim.x) {
        int g = m[i];
        int p = atomicAdd(&off[g], 1);
        g_perm[p] = i;
    }
}

// ---------------------------------------------------------------------------
// Kernel 2: FC1 GEMM (bf16 mma.sync).  64x128 tile, K=784 (49 x BK16).
// A rows gathered via g_perm, converted fp32->bf16 on the fly.
// Epilogue: +bias, ReLU, store bf16 to g_h1 in permuted (dense) row order.
// ---------------------------------------------------------------------------
__global__ __launch_bounds__(256, 2) void fc1_kernel(const float* __restrict__ x,
                                                     const float* __restrict__ tab) {
    const int tile = blockIdx.y;
    const int rows = g_tileRows[tile];
    if (rows == 0) return;
    const int grp   = g_tileGroup[tile];
    const int start = g_tileStart[tile];
    const int n0    = blockIdx.x * 128;
    const float* W  = tab + (size_t)grp * ((IN_DIM + 1) * HIDDEN);

    __shared__ __align__(16) __nv_bfloat16 As[2][64][24];    // 16 + 8 pad
    __shared__ __align__(16) __nv_bfloat16 Bs[2][16][136];   // 128 + 8 pad
    __shared__ int rowIdx[64];

    const int t = threadIdx.x, lane = t & 31, warp = t >> 5;
    const int wm = warp >> 2, wn = warp & 3;            // 2 x 4 warp grid

    if (t < 64) rowIdx[t] = (t < rows) ? g_perm[start + t] : -1;
    __syncthreads();

    // Fixed per-thread load coordinates
    int ac2[2]; const float* aptr[2];
#pragma unroll
    for (int p = 0; p < 2; p++) {
        int idx = t + p * 256;
        int r = idx >> 3; ac2[p] = idx & 7;             // 8 float2 per 16-wide row
        int gr = rowIdx[r];
        aptr[p] = (gr >= 0) ? x + (size_t)gr * IN_DIM + ac2[p] * 2 : nullptr;
    }
    int ar_s[2];
#pragma unroll
    for (int p = 0; p < 2; p++) ar_s[p] = (t + p * 256) >> 3;
    int br[4], bc2[4];
#pragma unroll
    for (int p = 0; p < 4; p++) { int idx = t + p * 256; br[p] = idx >> 6; bc2[p] = idx & 63; }

    float acc[2][4][4];
#pragma unroll
    for (int mi = 0; mi < 2; mi++)
#pragma unroll
        for (int ni = 0; ni < 4; ni++)
#pragma unroll
            for (int j = 0; j < 4; j++) acc[mi][ni][j] = 0.f;

    float2 aL[2], bL[4];
    // Prologue: tile 0
#pragma unroll
    for (int p = 0; p < 2; p++)
        aL[p] = aptr[p] ? *(const float2*)(aptr[p]) : make_float2(0.f, 0.f);
#pragma unroll
    for (int p = 0; p < 4; p++)
        bL[p] = *(const float2*)&W[(size_t)br[p] * HIDDEN + n0 + bc2[p] * 2];
#pragma unroll
    for (int p = 0; p < 2; p++)
        *(uint32_t*)&As[0][ar_s[p]][ac2[p] * 2] = f2bf2(aL[p].x, aL[p].y);
#pragma unroll
    for (int p = 0; p < 4; p++)
        *(uint32_t*)&Bs[0][br[p]][bc2[p] * 2] = f2bf2(bL[p].x, bL[p].y);
    __syncthreads();

    const int NIT = IN_DIM / 16;    // 49
    for (int it = 0; it < NIT; ++it) {
        const int cur = it & 1;
        if (it + 1 < NIT) {
            const int k0 = (it + 1) * 16;
#pragma unroll
            for (int p = 0; p < 2; p++)
                aL[p] = aptr[p] ? *(const float2*)(aptr[p] + k0) : make_float2(0.f, 0.f);
#pragma unroll
            for (int p = 0; p < 4; p++)
                bL[p] = *(const float2*)&W[(size_t)(k0 + br[p]) * HIDDEN + n0 + bc2[p] * 2];
        }

        uint32_t a[2][4], b[4][2];
#pragma unroll
        for (int mi = 0; mi < 2; mi++) {
            uint32_t sa = (uint32_t)__cvta_generic_to_shared(
                &As[cur][wm * 32 + mi * 16 + (lane & 15)][(lane >> 4) * 8]);
            ldsm_x4(a[mi][0], a[mi][1], a[mi][2], a[mi][3], sa);
        }
#pragma unroll
        for (int half = 0; half < 2; half++) {
            uint32_t sb = (uint32_t)__cvta_generic_to_shared(
                &Bs[cur][(lane & 7) + ((lane >> 3) & 1) * 8]
                   [wn * 32 + half * 16 + (lane >> 4) * 8]);
            ldsm_x4_t(b[2 * half][0], b[2 * half][1], b[2 * half + 1][0], b[2 * half + 1][1], sb);
        }
#pragma unroll
        for (int mi = 0; mi < 2; mi++)
#pragma unroll
            for (int ni = 0; ni < 4; ni++)
                mma16816(acc[mi][ni], a[mi], b[ni]);

        if (it + 1 < NIT) {
            const int nxt = cur ^ 1;
#pragma unroll
            for (int p = 0; p < 2; p++)
                *(uint32_t*)&As[nxt][ar_s[p]][ac2[p] * 2] = f2bf2(aL[p].x, aL[p].y);
#pragma unroll
            for (int p = 0; p < 4; p++)
                *(uint32_t*)&Bs[nxt][br[p]][bc2[p] * 2] = f2bf2(bL[p].x, bL[p].y);
        }
        __syncthreads();
    }

    // Epilogue: +bias, ReLU, bf16 store to g_h1 (permuted dense rows)
    const float* bias = W + (size_t)IN_DIM * HIDDEN + n0;
    uint32_t* h1u = (uint32_t*)g_h1;
#pragma unroll
    for (int ni = 0; ni < 4; ni++) {
        int c = wn * 32 + ni * 8 + (lane & 3) * 2;
        float2 bb = *(const float2*)&bias[c];
#pragma unroll
        for (int mi = 0; mi < 2; mi++) {
            int r0 = wm * 32 + mi * 16 + (lane >> 2);
            if (r0 < rows) {
                float vx = fmaxf(acc[mi][ni][0] + bb.x, 0.f);
                float vy = fmaxf(acc[mi][ni][1] + bb.y, 0.f);
                h1u[((size_t)(start + r0) * HIDDEN + n0 + c) >> 1] = f2bf2(vx, vy);
            }
            int r1 = r0 + 8;
            if (r1 < rows) {
                float vx = fmaxf(acc[mi][ni][2] + bb.x, 0.f);
                float vy = fmaxf(acc[mi][ni][3] + bb.y, 0.f);
                h1u[((size_t)(start + r1) * HIDDEN + n0 + c) >> 1] = f2bf2(vx, vy);
            }
        }
    }
}

// ---------------------------------------------------------------------------
// Kernel 3: FC2 GEMM (bf16 mma.sync).  64x128 tile, K=512 (32 x BK16).
// A = g_h1 (already bf16, permuted dense).  Epilogue: +bias, sigmoid,
// scatter fp32 to d_out via g_perm.
// ---------------------------------------------------------------------------
__global__ __launch_bounds__(256, 2) void fc2_kernel(const float* __restrict__ tab,
                                                     float* __restrict__ out) {
    const int tile = blockIdx.x;
    const int rows = g_tileRows[tile];
    if (rows == 0) return;
    const int grp   = g_tileGroup[tile];
    const int start = g_tileStart[tile];
    const float* W  = tab + (size_t)grp * ((HIDDEN + 1) * STYLE);

    __shared__ __align__(16) __nv_bfloat16 As[2][64][24];
    __shared__ __align__(16) __nv_bfloat16 Bs[2][16][136];
    __shared__ int rowIdx[64];

    const int t = threadIdx.x, lane = t & 31, warp = t >> 5;
    const int wm = warp >> 2, wn = warp & 3;

    if (t < 64) rowIdx[t] = (t < rows) ? g_perm[start + t] : -1;
    __syncthreads();

    // A: bf16 straight from g_h1 (uint32 = bf16x2)
    int ar_s[2], au[2]; const uint32_t* aptr[2];
    const uint32_t* h1u = (const uint32_t*)g_h1;
#pragma unroll
    for (int p = 0; p < 2; p++) {
        int idx = t + p * 256;
        ar_s[p] = idx >> 3; au[p] = idx & 7;            // 8 u32 per 16-wide row
        aptr[p] = h1u + (size_t)(start + ar_s[p]) * (HIDDEN / 2) + au[p];
    }
    int br[4], bc2[4];
#pragma unroll
    for (int p = 0; p < 4; p++) { int idx = t + p * 256; br[p] = idx >> 6; bc2[p] = idx & 63; }

    float acc[2][4][4];
#pragma unroll
    for (int mi = 0; mi < 2; mi++)
#pragma unroll
        for (int ni = 0; ni < 4; ni++)
#pragma unroll
            for (int j = 0; j < 4; j++) acc[mi][ni][j] = 0.f;

    uint32_t aL[2]; float2 bL[4];
#pragma unroll
    for (int p = 0; p < 2; p++) aL[p] = aptr[p][0];
#pragma unroll
    for (int p = 0; p < 4; p++)
        bL[p] = *(const float2*)&W[(size_t)br[p] * STYLE + bc2[p] * 2];
#pragma unroll
    for (int p = 0; p < 2; p++) *(uint32_t*)&As[0][ar_s[p]][au[p] * 2] = aL[p];
#pragma unroll
    for (int p = 0; p < 4; p++) *(uint32_t*)&Bs[0][br[p]][bc2[p] * 2] = f2bf2(bL[p].x, bL[p].y);
    __syncthreads();

    const int NIT = HIDDEN / 16;    // 32
    for (int it = 0; it < NIT; ++it) {
        const int cur = it & 1;
        if (it + 1 < NIT) {
            const int k0 = (it + 1) * 16;
#pragma unroll
            for (int p = 0; p < 2; p++) aL[p] = aptr[p][k0 >> 1];
#pragma unroll
            for (int p = 0; p < 4; p++)
                bL[p] = *(const float2*)&W[(size_t)(k0 + br[p]) * STYLE + bc2[p] * 2];
        }

        uint32_t a[2][4], b[4][2];
#pragma unroll
        for (int mi = 0; mi < 2; mi++) {
            uint32_t sa = (uint32_t)__cvta_generic_to_shared(
                &As[cur][wm * 32 + mi * 16 + (lane & 15)][(lane >> 4) * 8]);
            ldsm_x4(a[mi][0], a[mi][1], a[mi][2], a[mi][3], sa);
        }
#pragma unroll
        for (int half = 0; half < 2; half++) {
            uint32_t sb = (uint32_t)__cvta_generic_to_shared(
                &Bs[cur][(lane & 7) + ((lane >> 3) & 1) * 8]
                   [wn * 32 + half * 16 + (lane >> 4) * 8]);
            ldsm_x4_t(b[2 * half][0], b[2 * half][1], b[2 * half + 1][0], b[2 * half + 1][1], sb);
        }
#pragma unroll
        for (int mi = 0; mi < 2; mi++)
#pragma unroll
            for (int ni = 0; ni < 4; ni++)
                mma16816(acc[mi][ni], a[mi], b[ni]);

        if (it + 1 < NIT) {
            const int nxt = cur ^ 1;
#pragma unroll
            for (int p = 0; p < 2; p++) *(uint32_t*)&As[nxt][ar_s[p]][au[p] * 2] = aL[p];
#pragma unroll
            for (int p = 0; p < 4; p++)
                *(uint32_t*)&Bs[nxt][br[p]][bc2[p] * 2] = f2bf2(bL[p].x, bL[p].y);
        }
        __syncthreads();
    }

    // Epilogue: +bias, sigmoid, scatter fp32
    const float* bias = W + (size_t)HIDDEN * STYLE;
#pragma unroll
    for (int ni = 0; ni < 4; ni++) {
        int c = wn * 32 + ni * 8 + (lane & 3) * 2;
        float2 bb = *(const float2*)&bias[c];
#pragma unroll
        for (int mi = 0; mi < 2; mi++) {
            int r0 = wm * 32 + mi * 16 + (lane >> 2);
            if (r0 < rows) {
                int orow = rowIdx[r0];
                float2 v;
                v.x = 1.f / (1.f + __expf(-(acc[mi][ni][0] + bb.x)));
                v.y = 1.f / (1.f + __expf(-(acc[mi][ni][1] + bb.y)));
                *(float2*)&out[(size_t)orow * STYLE + c] = v;
            }
            int r1 = r0 + 8;
            if (r1 < rows) {
                int orow = rowIdx[r1];
                float2 v;
                v.x = 1.f / (1.f + __expf(-(acc[mi][ni][2] + bb.x)));
                v.y = 1.f / (1.f + __expf(-(acc[mi][ni][3] + bb.y)));
                *(float2*)&out[(size_t)orow * STYLE + c] = v;
            }
        }
    }
}

extern "C" void kernel_launch(void* const* d_in, const int* in_sizes, int n_in,
                              void* d_out, int out_size) {
    const float* x         = (const float*)d_in[0];
    const int*   m         = (const int*)d_in[1];
    const float* fc1_table = (const float*)d_in[2];
    const float* fc2_table = (const float*)d_in[3];
    float*       out       = (float*)d_out;

    group_kernel<<<1, 1024>>>(m);
    fc1_kernel<<<dim3(HIDDEN / 128, MAX_TILES), 256>>>(x, fc1_table);
    fc2_kernel<<<MAX_TILES, 256>>>(fc2_table, out);
}

// round 5
// speedup vs baseline: 5.5897x; 1.1739x over previous
#include <cuda_runtime.h>
#include <cuda_bf16.h>
#include <math.h>
#include <stdint.h>

#define IN_DIM   784
#define HIDDEN   512
#define STYLE    128
#define BATCH    2048
#define NUM_LABELS 10

#define BM 64
#define MAX_TILES (BATCH / BM + NUM_LABELS)   // 42

// Scratch (no allocations allowed -> __device__ globals)
__device__ int   g_perm[BATCH];
__device__ int   g_tileGroup[MAX_TILES];
__device__ int   g_tileStart[MAX_TILES];
__device__ int   g_tileRows[MAX_TILES];
__device__ __nv_bfloat16 g_h1[(BATCH + BM) * HIDDEN];  // bf16, padded one tile

// ---------------------------------------------------------------------------
// Helpers
// ---------------------------------------------------------------------------
__device__ __forceinline__ uint32_t f2bf2(float lo, float hi) {
    __nv_bfloat162 h = __floats2bfloat162_rn(lo, hi);   // .x = lo (low half)
    return *reinterpret_cast<uint32_t*>(&h);
}

__device__ __forceinline__ void ldsm_x4(uint32_t& r0, uint32_t& r1, uint32_t& r2, uint32_t& r3,
                                        uint32_t saddr) {
    asm volatile("ldmatrix.sync.aligned.m8n8.x4.shared.b16 {%0,%1,%2,%3}, [%4];"
                 : "=r"(r0), "=r"(r1), "=r"(r2), "=r"(r3) : "r"(saddr));
}

__device__ __forceinline__ void ldsm_x4_t(uint32_t& r0, uint32_t& r1, uint32_t& r2, uint32_t& r3,
                                          uint32_t saddr) {
    asm volatile("ldmatrix.sync.aligned.m8n8.x4.trans.shared.b16 {%0,%1,%2,%3}, [%4];"
                 : "=r"(r0), "=r"(r1), "=r"(r2), "=r"(r3) : "r"(saddr));
}

__device__ __forceinline__ void mma16816(float* c, const uint32_t* a, const uint32_t* b) {
    asm volatile("mma.sync.aligned.m16n8k16.row.col.f32.bf16.bf16.f32 "
                 "{%0,%1,%2,%3}, {%4,%5,%6,%7}, {%8,%9}, {%0,%1,%2,%3};"
                 : "+f"(c[0]), "+f"(c[1]), "+f"(c[2]), "+f"(c[3])
                 : "r"(a[0]), "r"(a[1]), "r"(a[2]), "r"(b[0]), "r"(a[3]), "r"(b[1])
                 );
}
// NOTE: operand order fixed below (a0..a3 then b0,b1) — see corrected version.
__device__ __forceinline__ void mma16816_c(float* c, const uint32_t* a, const uint32_t* b) {
    asm volatile("mma.sync.aligned.m16n8k16.row.col.f32.bf16.bf16.f32 "
                 "{%0,%1,%2,%3}, {%4,%5,%6,%7}, {%8,%9}, {%0,%1,%2,%3};"
                 : "+f"(c[0]), "+f"(c[1]), "+f"(c[2]), "+f"(c[3])
                 : "r"(a[0]), "r"(a[1]), "r"(a[2]), "r"(a[3]), "r"(b[0]), "r"(b[1]));
}

// ---------------------------------------------------------------------------
// Kernel 1: group samples by label. Warp-aggregated counting sort:
// __match_any + one atomic per distinct label per warp (was ~4096 serialized
// shared atomics to 10 addresses). Output values are order-invariant, so
// within-group order nondeterminism does not change d_out.
// ---------------------------------------------------------------------------
__global__ void group_kernel(const int* __restrict__ m) {
    __shared__ int cnt[NUM_LABELS];
    __shared__ int off[NUM_LABELS];
    const int t = threadIdx.x;          // 1024 threads, 2 elements each
    const int lane = t & 31;
    if (t < NUM_LABELS) cnt[t] = 0;
    __syncthreads();

    const int g0 = m[t];
    const int g1 = m[t + 1024];
    unsigned mk0 = __match_any_sync(0xffffffffu, g0);
    if ((__ffs(mk0) - 1) == lane) atomicAdd(&cnt[g0], __popc(mk0));
    unsigned mk1 = __match_any_sync(0xffffffffu, g1);
    if ((__ffs(mk1) - 1) == lane) atomicAdd(&cnt[g1], __popc(mk1));
    __syncthreads();

    if (t == 0) {
        int o = 0, tile = 0;
        for (int g = 0; g < NUM_LABELS; g++) {
            off[g] = o;
            int c = cnt[g];
            int nt = (c + BM - 1) / BM;
            for (int j = 0; j < nt; j++) {
                g_tileGroup[tile] = g;
                g_tileStart[tile] = o + j * BM;
                g_tileRows[tile]  = min(BM, c - j * BM);
                tile++;
            }
            o += c;
        }
        for (; tile < MAX_TILES; tile++) g_tileRows[tile] = 0;
    }
    __syncthreads();

    {
        int leader = __ffs(mk0) - 1;
        int base = 0;
        if (lane == leader) base = atomicAdd(&off[g0], __popc(mk0));
        base = __shfl_sync(0xffffffffu, base, leader);
        g_perm[base + __popc(mk0 & ((1u << lane) - 1u))] = t;
    }
    {
        int leader = __ffs(mk1) - 1;
        int base = 0;
        if (lane == leader) base = atomicAdd(&off[g1], __popc(mk1));
        base = __shfl_sync(0xffffffffu, base, leader);
        g_perm[base + __popc(mk1 & ((1u << lane) - 1u))] = t + 1024;
    }
}

// ---------------------------------------------------------------------------
// Kernel 2: FC1 GEMM (bf16 mma.sync).  64x128 tile, BK=32, 25 iters
// (last iter covers k=768..783, zero-filled beyond 784).
// ---------------------------------------------------------------------------
__global__ __launch_bounds__(256, 2) void fc1_kernel(const float* __restrict__ x,
                                                     const float* __restrict__ tab) {
    const int tile = blockIdx.y;
    const int rows = g_tileRows[tile];
    if (rows == 0) return;
    const int grp   = g_tileGroup[tile];
    const int start = g_tileStart[tile];
    const int n0    = blockIdx.x * 128;
    const float* W  = tab + (size_t)grp * ((IN_DIM + 1) * HIDDEN);

    __shared__ __align__(16) __nv_bfloat16 As[2][64][40];    // 32 + 8 pad
    __shared__ __align__(16) __nv_bfloat16 Bs[2][32][136];   // 128 + 8 pad
    __shared__ int rowIdx[64];

    const int t = threadIdx.x, lane = t & 31, warp = t >> 5;
    const int wm = warp >> 2, wn = warp & 3;            // 2 x 4 warp grid

    if (t < 64) rowIdx[t] = (t < rows) ? g_perm[start + t] : -1;
    __syncthreads();

    // A loads: 64x32 fp32 = 512 float4, 2/thread
    int ar[2], ac4[2], alim[2]; const float* aptr[2];
#pragma unroll
    for (int p = 0; p < 2; p++) {
        int idx = t + p * 256;
        ar[p] = idx >> 3; ac4[p] = idx & 7;
        int gr = rowIdx[ar[p]];
        aptr[p] = x + (size_t)max(gr, 0) * IN_DIM + ac4[p] * 4;
        alim[p] = (gr >= 0) ? (IN_DIM - ac4[p] * 4) : 0;   // valid iff k0 < alim
    }
    // B loads: 32x128 fp32 = 1024 float4, 4/thread
    int br[4], bc4[4];
#pragma unroll
    for (int p = 0; p < 4; p++) { int idx = t + p * 256; br[p] = idx >> 5; bc4[p] = idx & 31; }

    float acc[2][4][4];
#pragma unroll
    for (int mi = 0; mi < 2; mi++)
#pragma unroll
        for (int ni = 0; ni < 4; ni++)
#pragma unroll
            for (int j = 0; j < 4; j++) acc[mi][ni][j] = 0.f;

    const float4 Z4 = make_float4(0.f, 0.f, 0.f, 0.f);
    float4 aL[2], bL[4];
    // Prologue (k0 = 0): all k valid, only padded rows zero
#pragma unroll
    for (int p = 0; p < 2; p++)
        aL[p] = (alim[p] > 0) ? *(const float4*)(aptr[p]) : Z4;
#pragma unroll
    for (int p = 0; p < 4; p++)
        bL[p] = *(const float4*)&W[(size_t)br[p] * HIDDEN + n0 + bc4[p] * 4];
#pragma unroll
    for (int p = 0; p < 2; p++) {
        *(uint32_t*)&As[0][ar[p]][ac4[p] * 4]     = f2bf2(aL[p].x, aL[p].y);
        *(uint32_t*)&As[0][ar[p]][ac4[p] * 4 + 2] = f2bf2(aL[p].z, aL[p].w);
    }
#pragma unroll
    for (int p = 0; p < 4; p++) {
        *(uint32_t*)&Bs[0][br[p]][bc4[p] * 4]     = f2bf2(bL[p].x, bL[p].y);
        *(uint32_t*)&Bs[0][br[p]][bc4[p] * 4 + 2] = f2bf2(bL[p].z, bL[p].w);
    }
    __syncthreads();

    const int NIT = (IN_DIM + 31) / 32;    // 25 (last half-tile zero-filled)
    for (int it = 0; it < NIT; ++it) {
        const int cur = it & 1;
        if (it + 1 < NIT) {
            const int k0 = (it + 1) * 32;
#pragma unroll
            for (int p = 0; p < 2; p++)
                aL[p] = (k0 < alim[p]) ? *(const float4*)(aptr[p] + k0) : Z4;
#pragma unroll
            for (int p = 0; p < 4; p++) {
                int kr = k0 + br[p];
                const float4 v = *(const float4*)&W[(size_t)min(kr, IN_DIM) * HIDDEN + n0 + bc4[p] * 4];
                bL[p] = (kr < IN_DIM) ? v : Z4;
            }
        }

        uint32_t a[2][2][4], b[2][4][2];
#pragma unroll
        for (int mi = 0; mi < 2; mi++)
#pragma unroll
            for (int kh = 0; kh < 2; kh++) {
                uint32_t sa = (uint32_t)__cvta_generic_to_shared(
                    &As[cur][wm * 32 + mi * 16 + (lane & 15)][kh * 16 + (lane >> 4) * 8]);
                ldsm_x4(a[mi][kh][0], a[mi][kh][1], a[mi][kh][2], a[mi][kh][3], sa);
            }
#pragma unroll
        for (int kh = 0; kh < 2; kh++)
#pragma unroll
            for (int half = 0; half < 2; half++) {
                uint32_t sb = (uint32_t)__cvta_generic_to_shared(
                    &Bs[cur][kh * 16 + (lane & 7) + ((lane >> 3) & 1) * 8]
                       [wn * 32 + half * 16 + (lane >> 4) * 8]);
                ldsm_x4_t(b[kh][2 * half][0], b[kh][2 * half][1],
                          b[kh][2 * half + 1][0], b[kh][2 * half + 1][1], sb);
            }
#pragma unroll
        for (int kh = 0; kh < 2; kh++)
#pragma unroll
            for (int mi = 0; mi < 2; mi++)
#pragma unroll
                for (int ni = 0; ni < 4; ni++)
                    mma16816_c(acc[mi][ni], a[mi][kh], b[kh][ni]);

        if (it + 1 < NIT) {
            const int nxt = cur ^ 1;
#pragma unroll
            for (int p = 0; p < 2; p++) {
                *(uint32_t*)&As[nxt][ar[p]][ac4[p] * 4]     = f2bf2(aL[p].x, aL[p].y);
                *(uint32_t*)&As[nxt][ar[p]][ac4[p] * 4 + 2] = f2bf2(aL[p].z, aL[p].w);
            }
#pragma unroll
            for (int p = 0; p < 4; p++) {
                *(uint32_t*)&Bs[nxt][br[p]][bc4[p] * 4]     = f2bf2(bL[p].x, bL[p].y);
                *(uint32_t*)&Bs[nxt][br[p]][bc4[p] * 4 + 2] = f2bf2(bL[p].z, bL[p].w);
            }
        }
        __syncthreads();
    }

    // Epilogue: +bias, ReLU, bf16 store to g_h1 (permuted dense rows)
    const float* bias = W + (size_t)IN_DIM * HIDDEN + n0;
    uint32_t* h1u = (uint32_t*)g_h1;
#pragma unroll
    for (int ni = 0; ni < 4; ni++) {
        int c = wn * 32 + ni * 8 + (lane & 3) * 2;
        float2 bb = *(const float2*)&bias[c];
#pragma unroll
        for (int mi = 0; mi < 2; mi++) {
            int r0 = wm * 32 + mi * 16 + (lane >> 2);
            if (r0 < rows) {
                float vx = fmaxf(acc[mi][ni][0] + bb.x, 0.f);
                float vy = fmaxf(acc[mi][ni][1] + bb.y, 0.f);
                h1u[((size_t)(start + r0) * HIDDEN + n0 + c) >> 1] = f2bf2(vx, vy);
            }
            int r1 = r0 + 8;
            if (r1 < rows) {
                float vx = fmaxf(acc[mi][ni][2] + bb.x, 0.f);
                float vy = fmaxf(acc[mi][ni][3] + bb.y, 0.f);
                h1u[((size_t)(start + r1) * HIDDEN + n0 + c) >> 1] = f2bf2(vx, vy);
            }
        }
    }
}

// ---------------------------------------------------------------------------
// Kernel 3: FC2 GEMM (bf16 mma.sync).  64x128 tile, BK=32, 16 iters.
// A = g_h1 (already bf16, permuted dense).
// ---------------------------------------------------------------------------
__global__ __launch_bounds__(256, 2) void fc2_kernel(const float* __restrict__ tab,
                                                     float* __restrict__ out) {
    const int tile = blockIdx.x;
    const int rows = g_tileRows[tile];
    if (rows == 0) return;
    const int grp   = g_tileGroup[tile];
    const int start = g_tileStart[tile];
    const float* W  = tab + (size_t)grp * ((HIDDEN + 1) * STYLE);

    __shared__ __align__(16) __nv_bfloat16 As[2][64][40];
    __shared__ __align__(16) __nv_bfloat16 Bs[2][32][136];
    __shared__ int rowIdx[64];

    const int t = threadIdx.x, lane = t & 31, warp = t >> 5;
    const int wm = warp >> 2, wn = warp & 3;

    if (t < 64) rowIdx[t] = (t < rows) ? g_perm[start + t] : -1;
    __syncthreads();

    // A loads: 64x32 bf16 = 256 uint4 (16B), 1/thread
    const int ar = t >> 2, ah = t & 3;
    const uint4* aptr = (const uint4*)(g_h1 + (size_t)(start + ar) * HIDDEN + ah * 8);
    // B loads: 32x128 fp32 = 1024 float4, 4/thread (K=512, always in range)
    int br[4], bc4[4];
#pragma unroll
    for (int p = 0; p < 4; p++) { int idx = t + p * 256; br[p] = idx >> 5; bc4[p] = idx & 31; }

    float acc[2][4][4];
#pragma unroll
    for (int mi = 0; mi < 2; mi++)
#pragma unroll
        for (int ni = 0; ni < 4; ni++)
#pragma unroll
            for (int j = 0; j < 4; j++) acc[mi][ni][j] = 0.f;

    uint4 aL; float4 bL[4];
    aL = aptr[0];
#pragma unroll
    for (int p = 0; p < 4; p++)
        bL[p] = *(const float4*)&W[(size_t)br[p] * STYLE + bc4[p] * 4];
    *(uint4*)&As[0][ar][ah * 8] = aL;
#pragma unroll
    for (int p = 0; p < 4; p++) {
        *(uint32_t*)&Bs[0][br[p]][bc4[p] * 4]     = f2bf2(bL[p].x, bL[p].y);
        *(uint32_t*)&Bs[0][br[p]][bc4[p] * 4 + 2] = f2bf2(bL[p].z, bL[p].w);
    }
    __syncthreads();

    const int NIT = HIDDEN / 32;    // 16
    for (int it = 0; it < NIT; ++it) {
        const int cur = it & 1;
        if (it + 1 < NIT) {
            const int k0 = (it + 1) * 32;
            aL = *(const uint4*)((const __nv_bfloat16*)aptr + k0);
#pragma unroll
            for (int p = 0; p < 4; p++)
                bL[p] = *(const float4*)&W[(size_t)(k0 + br[p]) * STYLE + bc4[p] * 4];
        }

        uint32_t a[2][2][4], b[2][4][2];
#pragma unroll
        for (int mi = 0; mi < 2; mi++)
#pragma unroll
            for (int kh = 0; kh < 2; kh++) {
                uint32_t sa = (uint32_t)__cvta_generic_to_shared(
                    &As[cur][wm * 32 + mi * 16 + (lane & 15)][kh * 16 + (lane >> 4) * 8]);
                ldsm_x4(a[mi][kh][0], a[mi][kh][1], a[mi][kh][2], a[mi][kh][3], sa);
            }
#pragma unroll
        for (int kh = 0; kh < 2; kh++)
#pragma unroll
            for (int half = 0; half < 2; half++) {
                uint32_t sb = (uint32_t)__cvta_generic_to_shared(
                    &Bs[cur][kh * 16 + (lane & 7) + ((lane >> 3) & 1) * 8]
                       [wn * 32 + half * 16 + (lane >> 4) * 8]);
                ldsm_x4_t(b[kh][2 * half][0], b[kh][2 * half][1],
                          b[kh][2 * half + 1][0], b[kh][2 * half + 1][1], sb);
            }
#pragma unroll
        for (int kh = 0; kh < 2; kh++)
#pragma unroll
            for (int mi = 0; mi < 2; mi++)
#pragma unroll
                for (int ni = 0; ni < 4; ni++)
                    mma16816_c(acc[mi][ni], a[mi][kh], b[kh][ni]);

        if (it + 1 < NIT) {
            const int nxt = cur ^ 1;
            *(uint4*)&As[nxt][ar][ah * 8] = aL;
#pragma unroll
            for (int p = 0; p < 4; p++) {
                *(uint32_t*)&Bs[nxt][br[p]][bc4[p] * 4]     = f2bf2(bL[p].x, bL[p].y);
                *(uint32_t*)&Bs[nxt][br[p]][bc4[p] * 4 + 2] = f2bf2(bL[p].z, bL[p].w);
            }
        }
        __syncthreads();
    }

    // Epilogue: +bias, sigmoid, scatter fp32
    const float* bias = W + (size_t)HIDDEN * STYLE;
#pragma unroll
    for (int ni = 0; ni < 4; ni++) {
        int c = wn * 32 + ni * 8 + (lane & 3) * 2;
        float2 bb = *(const float2*)&bias[c];
#pragma unroll
        for (int mi = 0; mi < 2; mi++) {
            int r0 = wm * 32 + mi * 16 + (lane >> 2);
            if (r0 < rows) {
                int orow = rowIdx[r0];
                float2 v;
                v.x = 1.f / (1.f + __expf(-(acc[mi][ni][0] + bb.x)));
                v.y = 1.f / (1.f + __expf(-(acc[mi][ni][1] + bb.y)));
                *(float2*)&out[(size_t)orow * STYLE + c] = v;
            }
            int r1 = r0 + 8;
            if (r1 < rows) {
                int orow = rowIdx[r1];
                float2 v;
                v.x = 1.f / (1.f + __expf(-(acc[mi][ni][2] + bb.x)));
                v.y = 1.f / (1.f + __expf(-(acc[mi][ni][3] + bb.y)));
                *(float2*)&out[(size_t)orow * STYLE + c] = v;
            }
        }
    }
}

extern "C" void kernel_launch(void* const* d_in, const int* in_sizes, int n_in,
                              void* d_out, int out_size) {
    const float* x         = (const float*)d_in[0];
    const int*   m         = (const int*)d_in[1];
    const float* fc1_table = (const float*)d_in[2];
    const float* fc2_table = (const float*)d_in[3];
    float*       out       = (float*)d_out;

    group_kernel<<<1, 1024>>>(m);
    fc1_kernel<<<dim3(HIDDEN / 128, MAX_TILES), 256>>>(x, fc1_table);
    fc2_kernel<<<MAX_TILES, 256>>>(fc2_table, out);
}